// round 8
// baseline (speedup 1.0000x reference)
#include <cuda_runtime.h>

// Problem constants
#define H_   128
#define W_   128
#define BATCH 8
#define CIN  256
#define HWSZ (H_*W_)          // 16384
#define KKT  49

// Scratch (allocation-free rule: __device__ globals)
__device__ float g_part[BATCH * 2 * 2 * HWSZ];  // [b][half][{sum,max}][hw]
__device__ float g_att [BATCH * 2 * HWSZ];      // [b][{avg,max}][h][w]
__device__ float g_attn[BATCH * HWSZ];          // final sigmoid attention

typedef unsigned long long ull;

__device__ __forceinline__ ull pk2(float lo, float hi) {
    ull r; asm("mov.b64 %0, {%1, %2};" : "=l"(r) : "f"(lo), "f"(hi)); return r;
}
__device__ __forceinline__ ull fma2(ull a, ull b, ull c) {
    ull d; asm("fma.rn.f32x2 %0, %1, %2, %3;" : "=l"(d) : "l"(a), "l"(b), "l"(c)); return d;
}
__device__ __forceinline__ float psum2(ull v) {
    float lo, hi; asm("mov.b64 {%0, %1}, %2;" : "=f"(lo), "=f"(hi) : "l"(v)); return lo + hi;
}
__device__ __forceinline__ float sigmoidf_(float v) {
    return 1.f / (1.f + __expf(-v));
}

// ---------------------------------------------------------------------------
// K1a: partial channel mean+max.  Each thread reduces 128 of 256 channels for
// one float4 of pixels (split-C x2 for occupancy), loads batched x8 for MLP.
// ---------------------------------------------------------------------------
__global__ __launch_bounds__(256) void reduce_part_kernel(const float* __restrict__ x) {
    int i = blockIdx.x * 256 + threadIdx.x;        // [0, B*2*4096)
    int hw4  = i & 4095;
    int rest = i >> 12;                            // [0, 16)
    int b    = rest >> 1;
    int half = rest & 1;
    const float4* xp = (const float4*)(x + (size_t)b * CIN * HWSZ)
                       + (size_t)half * 128 * (HWSZ / 4) + hw4;
    float4 s = make_float4(0.f, 0.f, 0.f, 0.f);
    const float NEG = -3.402823466e38f;
    float4 m = make_float4(NEG, NEG, NEG, NEG);
    #pragma unroll 1
    for (int c = 0; c < 128; c += 8) {
        float4 v[8];
        #pragma unroll
        for (int u = 0; u < 8; ++u) v[u] = __ldg(xp + (c + u) * (HWSZ / 4));
        #pragma unroll
        for (int u = 0; u < 8; ++u) {
            s.x += v[u].x; s.y += v[u].y; s.z += v[u].z; s.w += v[u].w;
            m.x = fmaxf(m.x, v[u].x); m.y = fmaxf(m.y, v[u].y);
            m.z = fmaxf(m.z, v[u].z); m.w = fmaxf(m.w, v[u].w);
        }
    }
    float4* pp = (float4*)(g_part + ((b * 2 + half) * 2) * HWSZ);
    pp[hw4]                = s;
    pp[(HWSZ / 4) + hw4]   = m;
}

// ---------------------------------------------------------------------------
// K1b: combine the two channel-halves into g_att (avg, max planes).
// ---------------------------------------------------------------------------
__global__ __launch_bounds__(256) void reduce_comb_kernel() {
    int i = blockIdx.x * 256 + threadIdx.x;        // [0, B*4096)
    int hw4 = i & 4095;
    int b   = i >> 12;
    const float4* p0 = (const float4*)(g_part + ((b * 2 + 0) * 2) * HWSZ);
    const float4* p1 = (const float4*)(g_part + ((b * 2 + 1) * 2) * HWSZ);
    float4 s0 = p0[hw4],               s1 = p1[hw4];
    float4 m0 = p0[(HWSZ / 4) + hw4],  m1 = p1[(HWSZ / 4) + hw4];
    const float inv = 1.f / 256.f;
    float4 s, m;
    s.x = (s0.x + s1.x) * inv; s.y = (s0.y + s1.y) * inv;
    s.z = (s0.z + s1.z) * inv; s.w = (s0.w + s1.w) * inv;
    m.x = fmaxf(m0.x, m1.x); m.y = fmaxf(m0.y, m1.y);
    m.z = fmaxf(m0.z, m1.z); m.w = fmaxf(m0.w, m1.w);
    ((float4*)(g_att + b * 2 * HWSZ))[hw4]        = s;
    ((float4*)(g_att + b * 2 * HWSZ + HWSZ))[hw4] = m;
}

// ---------------------------------------------------------------------------
// K2: fused offset-conv (98ch) + modulation-conv (49ch) + deformable conv +
// sigmoid, one thread per pixel.  Patch (2ch x 7x7 = 98 f32) lives in regs as
// 49 packed f32x2; weights broadcast from SMEM (row stride padded to 100
// floats = 400B so rows are 16B-aligned for LDS.128).
// SMEM map (floats): [0,9800) offset_w rows, [9800,14700) mod_w rows,
//                    [14700,+98) dconv_w, [14800,+98) offset_b, [14900,+49) mod_b
// ---------------------------------------------------------------------------
__global__ __launch_bounds__(256) void deform_kernel(
    const float* __restrict__ offw, const float* __restrict__ offb,
    const float* __restrict__ modw, const float* __restrict__ modb,
    const float* __restrict__ dcw)
{
    extern __shared__ float sm[];
    const int tid = threadIdx.x;
    for (int t = tid; t < 98 * 98; t += 256) sm[(t / 98) * 100 + (t % 98)] = offw[t];
    for (int t = tid; t < 49 * 98; t += 256) sm[9800 + (t / 98) * 100 + (t % 98)] = modw[t];
    if (tid < 98) sm[14700 + tid] = dcw[tid];
    if (tid < 98) sm[14800 + tid] = offb[tid];
    if (tid < 49) sm[14900 + tid] = modb[tid];
    __syncthreads();

    const int idx = blockIdx.x * 256 + tid;        // b*HWSZ + hw, exact grid
    const int b  = idx >> 14;
    const int hw = idx & (HWSZ - 1);
    const int h  = hw >> 7;
    const int w  = hw & 127;

    const float* __restrict__ a0 = g_att + b * 2 * HWSZ;  // avg channel
    const float* __restrict__ a1 = a0 + HWSZ;             // max channel

    // tap value (zero-padded conv input); t is compile-time in unrolled loops.
    auto tap = [&](const float* base, int t) -> float {
        int yy = h + (t / 7) - 3;
        int xx = w + (t % 7) - 3;
        bool ok = ((unsigned)yy < (unsigned)H_) & ((unsigned)xx < (unsigned)W_);
        return ok ? __ldg(base + (yy << 7) + xx) : 0.f;
    };

    // Packed patch: linear order [c0 taps 0..48, c1 taps 0..48] as f32x2 pairs.
    ull pr[49];
    #pragma unroll
    for (int i = 0; i < 24; ++i) pr[i] = pk2(tap(a0, 2 * i), tap(a0, 2 * i + 1));
    pr[24] = pk2(tap(a0, 48), tap(a1, 0));
    #pragma unroll
    for (int i = 0; i < 24; ++i) pr[25 + i] = pk2(tap(a1, 2 * i + 1), tap(a1, 2 * i + 2));

    float acc = 0.f;
    #pragma unroll 1
    for (int j = 0; j < KKT; ++j) {
        const ulonglong2* __restrict__ wy = (const ulonglong2*)(sm + (2 * j) * 100);
        const ulonglong2* __restrict__ wx = (const ulonglong2*)(sm + (2 * j + 1) * 100);
        const ulonglong2* __restrict__ wm = (const ulonglong2*)(sm + 9800 + j * 100);
        ull ay = pk2(0.f, 0.f);
        ull ax = ay, am = ay;
        #pragma unroll
        for (int q = 0; q < 24; ++q) {             // floats 4q..4q+3 of each row
            ulonglong2 A = wy[q];
            ulonglong2 B = wx[q];
            ulonglong2 C = wm[q];
            ull p0 = pr[2 * q], p1 = pr[2 * q + 1];
            ay = fma2(A.x, p0, ay);
            ax = fma2(B.x, p0, ax);
            am = fma2(C.x, p0, am);
            ay = fma2(A.y, p1, ay);
            ax = fma2(B.y, p1, ax);
            am = fma2(C.y, p1, am);
        }
        {   // tail pair: floats 96,97 (byte offset 384 within row, 8B aligned)
            ull p = pr[48];
            ay = fma2(*(const ull*)(sm + (2 * j) * 100 + 96), p, ay);
            ax = fma2(*(const ull*)(sm + (2 * j + 1) * 100 + 96), p, ax);
            am = fma2(*(const ull*)(sm + 9800 + j * 100 + 96), p, am);
        }
        // Uniform (thread-invariant) scalar loads: bias + dconv weights.
        float offy = psum2(ay) + sm[14800 + 2 * j];
        float offx = psum2(ax) + sm[14800 + 2 * j + 1];
        float mr   = psum2(am) + sm[14900 + j];
        float mask = 2.f * sigmoidf_(mr);

        float py = (float)(h + j / 7 - 3) + offy;
        float px = (float)(w + j % 7 - 3) + offx;
        float y0f = floorf(py), x0f = floorf(px);
        int   y0  = (int)y0f,  x0  = (int)x0f;
        float wy1 = py - y0f,  wx1 = px - x0f;
        float wy0 = 1.f - wy1, wx0 = 1.f - wx1;

        float s0 = 0.f, s1 = 0.f;
        #pragma unroll
        for (int cy = 0; cy < 2; ++cy) {
            #pragma unroll
            for (int cx = 0; cx < 2; ++cx) {
                int yi = y0 + cy, xi = x0 + cx;
                float wgt = (cy ? wy1 : wy0) * (cx ? wx1 : wx0);
                bool v = ((unsigned)yi < (unsigned)H_) & ((unsigned)xi < (unsigned)W_);
                int yc = min(max(yi, 0), H_ - 1);
                int xc = min(max(xi, 0), W_ - 1);
                float f = v ? wgt : 0.f;
                int o = (yc << 7) + xc;
                s0 += f * __ldg(a0 + o);
                s1 += f * __ldg(a1 + o);
            }
        }
        acc += mask * (sm[14700 + j] * s0 + sm[14700 + 49 + j] * s1);
    }
    g_attn[idx] = sigmoidf_(acc);
}

// ---------------------------------------------------------------------------
// K3: out = x * attn.  8 channels per thread: attn float4 loaded ONCE and
// reused across 8 channel planes -> attn LTS traffic cut 8x vs per-channel.
// x accesses stay fully coalesced (consecutive threads -> consecutive float4
// within a channel plane).
// ---------------------------------------------------------------------------
#define CPT 8   // channels per thread
__global__ __launch_bounds__(256) void mul_kernel(const float* __restrict__ x,
                                                  float* __restrict__ out)
{
    int i = blockIdx.x * 256 + threadIdx.x;
    int hw4 = i & (HWSZ / 4 - 1);                  // 4096 float4 per plane
    int bc  = i >> 12;                             // b * (CIN/CPT) + cgrp
    int b    = bc >> 5;                            // CIN/CPT = 32 groups
    int cgrp = bc & 31;
    float4 av = *((const float4*)g_attn + b * (HWSZ / 4) + hw4);
    size_t base = ((size_t)b * CIN + (size_t)cgrp * CPT) * (HWSZ / 4) + hw4;
    #pragma unroll
    for (int c = 0; c < CPT; ++c) {
        float4 xv = __ldg((const float4*)x + base + c * (HWSZ / 4));
        float4 ov;
        ov.x = xv.x * av.x;
        ov.y = xv.y * av.y;
        ov.z = xv.z * av.z;
        ov.w = xv.w * av.w;
        ((float4*)out)[base + c * (HWSZ / 4)] = ov;
    }
}

// ---------------------------------------------------------------------------
extern "C" void kernel_launch(void* const* d_in, const int* in_sizes, int n_in,
                              void* d_out, int out_size)
{
    const float* x    = (const float*)d_in[0];
    const float* offw = (const float*)d_in[1];
    const float* offb = (const float*)d_in[2];
    const float* modw = (const float*)d_in[3];
    const float* modb = (const float*)d_in[4];
    const float* dcw  = (const float*)d_in[5];
    float* out = (float*)d_out;

    const int SMEM_BYTES = 14949 * 4;  // 59796 B > 48KB default -> opt-in
    cudaFuncSetAttribute(deform_kernel,
                         cudaFuncAttributeMaxDynamicSharedMemorySize, SMEM_BYTES);

    reduce_part_kernel<<<(BATCH * 2 * (HWSZ / 4)) / 256, 256>>>(x);
    reduce_comb_kernel<<<(BATCH * (HWSZ / 4)) / 256, 256>>>();
    deform_kernel<<<(BATCH * HWSZ) / 256, 256, SMEM_BYTES>>>(offw, offb, modw, modb, dcw);
    mul_kernel<<<(BATCH * (CIN / CPT) * (HWSZ / 4)) / 256, 256>>>(x, out);
}